// round 1
// baseline (speedup 1.0000x reference)
#include <cuda_runtime.h>
#include <cuda_bf16.h>

// Problem constants (fixed by reference setup_inputs)
#define BS       32
#define WIDTH    4
#define DEPTH    5
#define D_MODEL  1024
#define MAX_LEN  2048
#define N_FEAT   (D_MODEL / (WIDTH * DEPTH))   // 51
#define DW       (DEPTH * WIDTH)               // 20
#define N_NODES  1364                          // 4+16+64+256+1024
#define W_TABLE  (DEPTH * N_FEAT)              // 255

// Scratch for the weight table (tree_weights collapsed to [depth, n_feat])
__device__ float g_w[W_TABLE];

// Kernel 1: build_weights — tanh-parameterized geometric decay, exact ref formula
__global__ void build_weights_kernel(const float* __restrict__ p) {
    int idx = threadIdx.x;
    if (idx < W_TABLE) {
        int l = idx / N_FEAT;
        int f = idx - l * N_FEAT;
        float tp = tanhf(p[f]);
        float norm = sqrtf((1.0f - tp * tp) * (float)D_MODEL * 0.5f);
        float w = norm;
        #pragma unroll 4
        for (int i = 0; i < l; i++) w *= tp;   // tp^l * norm
        g_w[idx] = w;
    }
}

// Kernel 2: one block per sequence slot t (0..MAX_LEN-1).
// Thread tid owns channels [4*tid, 4*tid+4). Content is batch-invariant
// (positions is broadcast across batch in the reference), so each thread
// computes its float4 once and stores it for all 32 batches -> 32 independent
// STG.128 per thread = deep store MLP, fully coalesced within each warp.
__global__ void __launch_bounds__(256, 4)
encode_kernel(const float* __restrict__ positions,  // batch-0 slice [N_NODES, DW]
              float* __restrict__ out) {
    __shared__ float s_w[W_TABLE];
    __shared__ float s_pos[DW];

    const int t   = blockIdx.x;        // sequence position in [0, MAX_LEN)
    const int tid = threadIdx.x;       // channel-quad in [0, 256)

    if (tid < W_TABLE) s_w[tid] = g_w[tid];
    const bool is_node = (t >= 1) && (t <= N_NODES);
    if (tid < DW) s_pos[tid] = is_node ? positions[(size_t)(t - 1) * DW + tid] : 0.0f;
    __syncthreads();

    const int c = tid * 4;
    float4 v = make_float4(0.f, 0.f, 0.f, 0.f);
    if (is_node) {
        float r[4];
        #pragma unroll
        for (int k = 0; k < 4; k++) {
            int cc = c + k;
            int dw = cc / N_FEAT;              // which (level,child) channel
            int f  = cc - dw * N_FEAT;         // feature within channel
            // channels >= DW*N_FEAT (1020..1023) are the zero feature-pad
            r[k] = (dw < DW) ? s_pos[dw] * s_w[(dw / WIDTH) * N_FEAT + f] : 0.0f;
        }
        v = make_float4(r[0], r[1], r[2], r[3]);
    }

    // Broadcast-store to all batches: out[b, t, c..c+3]
    float* dst = out + (size_t)t * D_MODEL + c;
    #pragma unroll
    for (int b = 0; b < BS; b++) {
        *reinterpret_cast<float4*>(dst + (size_t)b * (MAX_LEN * D_MODEL)) = v;
    }
}

extern "C" void kernel_launch(void* const* d_in, const int* in_sizes, int n_in,
                              void* d_out, int out_size) {
    const float* p         = (const float*)d_in[0];   // [64] fp32
    const float* positions = (const float*)d_in[1];   // [BS, N_NODES, DW] fp32 (batch-broadcast)
    float* out = (float*)d_out;                        // [BS, MAX_LEN, D_MODEL] fp32

    build_weights_kernel<<<1, 256>>>(p);
    encode_kernel<<<MAX_LEN, 256>>>(positions, out);
}